// round 1
// baseline (speedup 1.0000x reference)
#include <cuda_runtime.h>
#include <math.h>

#define NN 50000
#define EE 800000
#define ET 850000          // EE + NN self loops
#define FH 128             // H * C
#define CC 64
#define NEG 0.2f
#define EPSN 1e-5f

// ---------------- scratch (static device, no allocation) ----------------
__device__ __align__(16) float g_xl[NN * FH];
__device__ __align__(16) float g_xr[NN * FH];
__device__ __align__(16) float g_accum[NN * FH];
__device__ float g_logit[ET * 2];
__device__ float g_m[NN * 2];
__device__ float g_z[NN * 2];
__device__ float g_cs[CC];
__device__ float g_css[CC];
__device__ __align__(16) float g_xpre[NN * CC];
__device__ __align__(16) float g_xcur[NN * CC];

// ---------------- helpers ----------------
__device__ __forceinline__ void atomicMaxF(float* addr, float v) {
    if (v >= 0.f) atomicMax((int*)addr, __float_as_int(v));
    else          atomicMin((unsigned int*)addr, __float_as_uint(v));
}

__device__ __forceinline__ float lrelu(float v) {
    return fmaxf(v, 0.f) + NEG * fminf(v, 0.f);
}

// ---------------- per-layer reset ----------------
__global__ void k_init() {
    int i = blockIdx.x * blockDim.x + threadIdx.x;   // grid covers NN*FH
    g_accum[i] = 0.f;
    if (i < NN * 2) { g_m[i] = -INFINITY; g_z[i] = 0.f; }
    if (i < CC)     { g_cs[i] = 0.f; g_css[i] = 0.f; }
}

// ---------------- xl = x@Wl, xr = x@Wr ----------------
// block = (128 j, 2 nodes); weight rows L1-cached, x broadcast.
__global__ void k_gemm(const float* __restrict__ xin,
                       const float* __restrict__ Wl,
                       const float* __restrict__ Wr, int din) {
    const float* xp = xin ? xin : g_xcur;
    int j = threadIdx.x;
    int node = blockIdx.x * 2 + threadIdx.y;         // NN even -> always valid
    const float* xrow = xp + (size_t)node * din;
    float al = 0.f, ar = 0.f;
    for (int k = 0; k < din; k++) {
        float xv = __ldg(xrow + k);
        al = fmaf(xv, __ldg(Wl + k * FH + j), al);
        ar = fmaf(xv, __ldg(Wr + k * FH + j), ar);
    }
    g_xl[node * FH + j] = al;
    g_xr[node * FH + j] = ar;
}

// ---------------- edge pass 1: logits + segment max ----------------
// 16 lanes per (edge, head) unit; coalesced 256B gathers from L2.
__global__ void k_logit(const int* __restrict__ ei,
                        const float* __restrict__ att) {
    int t = blockIdx.x * blockDim.x + threadIdx.x;   // exactly ET*2*16 threads
    int u = t >> 4, sub = t & 15;
    int e = u >> 1, h = u & 1;
    int s, d;
    if (e < EE) { s = __ldg(ei + e); d = __ldg(ei + EE + e); }
    else        { s = e - EE; d = s; }

    float4 a4 = ((const float4*)(g_xl + s * FH + h * CC))[sub];
    float4 b4 = ((const float4*)(g_xr + d * FH + h * CC))[sub];
    float4 w  = ((const float4*)(att + h * CC))[sub];

    float sum;
    sum  = lrelu(a4.x + b4.x) * w.x;
    sum += lrelu(a4.y + b4.y) * w.y;
    sum += lrelu(a4.z + b4.z) * w.z;
    sum += lrelu(a4.w + b4.w) * w.w;

    sum += __shfl_xor_sync(0xffffffffu, sum, 8);
    sum += __shfl_xor_sync(0xffffffffu, sum, 4);
    sum += __shfl_xor_sync(0xffffffffu, sum, 2);
    sum += __shfl_xor_sync(0xffffffffu, sum, 1);

    if (sub == 0) {
        g_logit[u] = sum;
        atomicMaxF(&g_m[d * 2 + h], sum);
    }
}

// ---------------- edge pass 2: exp, z-sum, weighted scatter-add ----------------
__global__ void k_agg(const int* __restrict__ ei) {
    int t = blockIdx.x * blockDim.x + threadIdx.x;
    int u = t >> 4, sub = t & 15;
    int e = u >> 1, h = u & 1;
    int s, d;
    if (e < EE) { s = __ldg(ei + e); d = __ldg(ei + EE + e); }
    else        { s = e - EE; d = s; }

    float a = __expf(g_logit[u] - g_m[d * 2 + h]);
    if (sub == 0) atomicAdd(&g_z[d * 2 + h], a);

    float4 xlv = ((const float4*)(g_xl + s * FH + h * CC))[sub];
    float* dst = g_accum + d * FH + h * CC + sub * 4;
    atomicAdd(dst + 0, a * xlv.x);
    atomicAdd(dst + 1, a * xlv.y);
    atomicAdd(dst + 2, a * xlv.z);
    atomicAdd(dst + 3, a * xlv.w);
}

// ---------------- node finalize: head mean + bias, column sum/sumsq ----------------
__global__ void k_final(const float* __restrict__ b) {
    __shared__ float ss[CC], sq[CC];
    int t = threadIdx.x;
    if (t < CC) { ss[t] = 0.f; sq[t] = 0.f; }
    __syncthreads();

    int idx = blockIdx.x * 256 + t;                  // grid covers NN*CC exactly
    int n = idx >> 6, c = idx & 63;
    float z0 = g_z[n * 2], z1 = g_z[n * 2 + 1];
    float v = 0.5f * (g_accum[n * FH + c] / z0 + g_accum[n * FH + CC + c] / z1)
            + __ldg(b + c);
    g_xpre[idx] = v;
    atomicAdd(&ss[c], v);
    atomicAdd(&sq[c], v * v);
    __syncthreads();
    if (t < CC) {
        atomicAdd(&g_cs[t],  ss[t]);
        atomicAdd(&g_css[t], sq[t]);
    }
}

// ---------------- graph norm + relu ----------------
__global__ void k_norm(const float* __restrict__ gw,
                       const float* __restrict__ gb,
                       const float* __restrict__ gm,
                       float* __restrict__ out_ext) {
    float* out = out_ext ? out_ext : g_xcur;
    int idx = blockIdx.x * blockDim.x + threadIdx.x;
    int c = idx & 63;
    float inv = 1.f / (float)NN;
    float mu  = g_cs[c]  * inv;
    float msq = g_css[c] * inv;
    float ms  = __ldg(gm + c);
    float var = msq - 2.f * ms * mu * mu + ms * ms * mu * mu;
    float o = g_xpre[idx] - ms * mu;
    float y = __ldg(gw + c) * o * rsqrtf(var + EPSN) + __ldg(gb + c);
    out[idx] = fmaxf(y, 0.f);
}

// ---------------- launch ----------------
extern "C" void kernel_launch(void* const* d_in, const int* in_sizes, int n_in,
                              void* d_out, int out_size) {
    const float* x  = (const float*)d_in[0];
    const int*   ei = (const int*)d_in[1];
    float* out = (float*)d_out;

    const float* xin = x;
    int din = 3;

    const int initBlocks  = (NN * FH) / 256;         // 25000
    const int edgeBlocks  = (ET * 2 * 16) / 256;     // 106250
    const int nodeBlocks  = (NN * CC) / 256;         // 12500

    for (int l = 0; l < 3; l++) {
        int base = 2 + 7 * l;
        const float* Wl  = (const float*)d_in[base + 0];
        const float* Wr  = (const float*)d_in[base + 1];
        const float* att = (const float*)d_in[base + 2];
        const float* b   = (const float*)d_in[base + 3];
        const float* gw  = (const float*)d_in[base + 4];
        const float* gb  = (const float*)d_in[base + 5];
        const float* gm  = (const float*)d_in[base + 6];

        k_init<<<initBlocks, 256>>>();
        k_gemm<<<NN / 2, dim3(128, 2)>>>(xin, Wl, Wr, din);
        k_logit<<<edgeBlocks, 256>>>(ei, att);
        k_agg<<<edgeBlocks, 256>>>(ei);
        k_final<<<nodeBlocks, 256>>>(b);
        k_norm<<<nodeBlocks, 256>>>(gw, gb, gm, (l == 2) ? out : nullptr);

        xin = nullptr;   // subsequent layers read g_xcur inside k_gemm
        din = CC;
    }
}

// round 3
// speedup vs baseline: 2.8146x; 2.8146x over previous
#include <cuda_runtime.h>
#include <math.h>

#define NN 50000
#define EE 800000
#define ET 850000          // EE + NN self loops
#define FH 128             // H * C
#define CC 64
#define NEG 0.2f
#define EPSN 1e-5f

// ---------------- scratch (static device, no allocation) ----------------
__device__ __align__(16) float g_xl[NN * FH];
__device__ __align__(16) float g_xr[NN * FH];
__device__ __align__(16) float g_xpre[NN * CC];
__device__ __align__(16) float g_xcur[NN * CC];
__device__ float g_cs[CC];
__device__ float g_css[CC];
__device__ int   g_deg[NN];
__device__ int   g_rowptr[NN + 1];
__device__ int   g_cursor[NN];
__device__ int   g_csrc[ET];

__device__ __forceinline__ float lrelu(float v) {
    return fmaxf(v, 0.f) + NEG * fminf(v, 0.f);
}

// ================= CSR build (once per launch, reused by all layers) ======
__global__ void k_zdeg() {
    int i = blockIdx.x * blockDim.x + threadIdx.x;
    if (i < NN) g_deg[i] = 0;
}

__global__ void k_histo(const int* __restrict__ ei) {
    int e = blockIdx.x * blockDim.x + threadIdx.x;
    if (e >= ET) return;
    int d = (e < EE) ? __ldg(ei + EE + e) : (e - EE);
    atomicAdd(&g_deg[d], 1);
}

// single-block exclusive scan over g_deg -> g_rowptr / g_cursor
__global__ void k_scan() {
    __shared__ int sh[1024];
    __shared__ int carry;
    int tid = threadIdx.x;
    if (tid == 0) carry = 0;
    __syncthreads();
    for (int base = 0; base < NN; base += 1024) {
        int i = base + tid;
        int v = (i < NN) ? g_deg[i] : 0;
        sh[tid] = v;
        __syncthreads();
        for (int off = 1; off < 1024; off <<= 1) {
            int t = (tid >= off) ? sh[tid - off] : 0;
            __syncthreads();
            sh[tid] += t;
            __syncthreads();
        }
        if (i < NN) {
            int excl = carry + sh[tid] - v;
            g_rowptr[i] = excl;
            g_cursor[i] = excl;
        }
        __syncthreads();
        if (tid == 0) carry += sh[1023];
        __syncthreads();
    }
    if (tid == 0) g_rowptr[NN] = carry;
}

__global__ void k_scatter(const int* __restrict__ ei) {
    int e = blockIdx.x * blockDim.x + threadIdx.x;
    if (e >= ET) return;
    int s, d;
    if (e < EE) { s = __ldg(ei + e); d = __ldg(ei + EE + e); }
    else        { s = e - EE; d = s; }
    int pos = atomicAdd(&g_cursor[d], 1);
    g_csrc[pos] = s;
}

// ================= per-layer kernels =====================================
__global__ void k_zero() {          // <<<1,64>>>
    g_cs[threadIdx.x] = 0.f;
    g_css[threadIdx.x] = 0.f;
}

// xl = x@Wl, xr = x@Wr.  block (32,8): lane -> 4 columns (float4),
// each thread-row handles 4 nodes -> 32 nodes per block.
__global__ void k_gemm(const float* __restrict__ xin,
                       const float* __restrict__ Wl,
                       const float* __restrict__ Wr, int din) {
    const float* xp = xin ? xin : g_xcur;
    int lane  = threadIdx.x;                       // 0..31
    int node0 = blockIdx.x * 32 + threadIdx.y * 4; // multiple of 4
    if (node0 >= NN) return;

    float4 al[4], ar[4];
#pragma unroll
    for (int nn = 0; nn < 4; nn++) {
        al[nn] = make_float4(0.f, 0.f, 0.f, 0.f);
        ar[nn] = make_float4(0.f, 0.f, 0.f, 0.f);
    }
    const float* x0 = xp + (size_t)node0 * din;
    for (int k = 0; k < din; k++) {
        float4 wl = *(const float4*)(Wl + k * FH + lane * 4);
        float4 wr = *(const float4*)(Wr + k * FH + lane * 4);
#pragma unroll
        for (int nn = 0; nn < 4; nn++) {
            float xv = __ldg(x0 + nn * din + k);
            al[nn].x = fmaf(xv, wl.x, al[nn].x);
            al[nn].y = fmaf(xv, wl.y, al[nn].y);
            al[nn].z = fmaf(xv, wl.z, al[nn].z);
            al[nn].w = fmaf(xv, wl.w, al[nn].w);
            ar[nn].x = fmaf(xv, wr.x, ar[nn].x);
            ar[nn].y = fmaf(xv, wr.y, ar[nn].y);
            ar[nn].z = fmaf(xv, wr.z, ar[nn].z);
            ar[nn].w = fmaf(xv, wr.w, ar[nn].w);
        }
    }
#pragma unroll
    for (int nn = 0; nn < 4; nn++) {
        *(float4*)(g_xl + (size_t)(node0 + nn) * FH + lane * 4) = al[nn];
        *(float4*)(g_xr + (size_t)(node0 + nn) * FH + lane * 4) = ar[nn];
    }
}

// Fused attention: warp per (node, head), online softmax, no float atomics.
// block 256 = 4 nodes x 2 heads. Also fuses head-mean + bias + column stats.
__global__ void k_attn(const float* __restrict__ att,
                       const float* __restrict__ b) {
    __shared__ float sh[8][CC];
    __shared__ float ss[CC], sq[CC];
    int tid  = threadIdx.x;
    int warp = tid >> 5, lane = tid & 31;
    int node = blockIdx.x * 4 + (warp >> 1);
    int h    = warp & 1;

    if (tid < CC) { ss[tid] = 0.f; sq[tid] = 0.f; }

    float2 xr2 = *(const float2*)(g_xr + (size_t)node * FH + h * CC + lane * 2);
    float2 w2  = *(const float2*)(att + h * CC + lane * 2);

    float m = -INFINITY, z = 0.f, a0 = 0.f, a1 = 0.f;
    int i0 = g_rowptr[node], i1 = g_rowptr[node + 1];
    for (int i = i0; i < i1; i++) {
        int s = __ldg(g_csrc + i);
        float2 xl2 = *(const float2*)(g_xl + (size_t)s * FH + h * CC + lane * 2);
        float p = lrelu(xl2.x + xr2.x) * w2.x + lrelu(xl2.y + xr2.y) * w2.y;
        p += __shfl_xor_sync(0xffffffffu, p, 16);
        p += __shfl_xor_sync(0xffffffffu, p, 8);
        p += __shfl_xor_sync(0xffffffffu, p, 4);
        p += __shfl_xor_sync(0xffffffffu, p, 2);
        p += __shfl_xor_sync(0xffffffffu, p, 1);
        float mn = fmaxf(m, p);
        float c  = __expf(m - mn);     // 1 if no new max; 0 on first edge
        float e  = __expf(p - mn);
        z  = z  * c + e;
        a0 = a0 * c + e * xl2.x;
        a1 = a1 * c + e * xl2.y;
        m = mn;
    }
    sh[warp][lane * 2]     = a0 / z;
    sh[warp][lane * 2 + 1] = a1 / z;
    __syncthreads();

    int nl = tid >> 6, c = tid & 63;
    float v = 0.5f * (sh[nl * 2][c] + sh[nl * 2 + 1][c]) + __ldg(b + c);
    g_xpre[(size_t)(blockIdx.x * 4 + nl) * CC + c] = v;
    atomicAdd(&ss[c], v);
    atomicAdd(&sq[c], v * v);
    __syncthreads();
    if (tid < CC) {
        atomicAdd(&g_cs[tid],  ss[tid]);
        atomicAdd(&g_css[tid], sq[tid]);
    }
}

// graph norm + relu
__global__ void k_norm(const float* __restrict__ gw,
                       const float* __restrict__ gb,
                       const float* __restrict__ gm,
                       float* __restrict__ out_ext) {
    float* out = out_ext ? out_ext : g_xcur;
    int idx = blockIdx.x * blockDim.x + threadIdx.x;
    int c = idx & 63;
    float inv = 1.f / (float)NN;
    float mu  = g_cs[c]  * inv;
    float msq = g_css[c] * inv;
    float ms  = __ldg(gm + c);
    float var = msq - 2.f * ms * mu * mu + ms * ms * mu * mu;
    float o = g_xpre[idx] - ms * mu;
    float y = __ldg(gw + c) * o * rsqrtf(var + EPSN) + __ldg(gb + c);
    out[idx] = fmaxf(y, 0.f);
}

// ---------------- launch ----------------
extern "C" void kernel_launch(void* const* d_in, const int* in_sizes, int n_in,
                              void* d_out, int out_size) {
    const float* x  = (const float*)d_in[0];
    const int*   ei = (const int*)d_in[1];
    float* out = (float*)d_out;

    const int edgeBlocks = (ET + 255) / 256;       // 3321
    const int gemmBlocks = (NN + 31) / 32;         // 1563
    const int attnBlocks = NN / 4;                 // 12500
    const int normBlocks = (NN * CC) / 256;        // 12500

    // CSR by dst, built once, reused by all 3 layers
    k_zdeg<<<(NN + 255) / 256, 256>>>();
    k_histo<<<edgeBlocks, 256>>>(ei);
    k_scan<<<1, 1024>>>();
    k_scatter<<<edgeBlocks, 256>>>(ei);

    const float* xin = x;
    int din = 3;
    for (int l = 0; l < 3; l++) {
        int base = 2 + 7 * l;
        const float* Wl  = (const float*)d_in[base + 0];
        const float* Wr  = (const float*)d_in[base + 1];
        const float* att = (const float*)d_in[base + 2];
        const float* b   = (const float*)d_in[base + 3];
        const float* gw  = (const float*)d_in[base + 4];
        const float* gb  = (const float*)d_in[base + 5];
        const float* gm  = (const float*)d_in[base + 6];

        k_zero<<<1, 64>>>();
        k_gemm<<<gemmBlocks, dim3(32, 8)>>>(xin, Wl, Wr, din);
        k_attn<<<attnBlocks, 256>>>(att, b);
        k_norm<<<normBlocks, 256>>>(gw, gb, gm, (l == 2) ? out : nullptr);

        xin = nullptr;    // subsequent layers read g_xcur
        din = CC;
    }
}

// round 4
// speedup vs baseline: 3.4149x; 1.2133x over previous
#include <cuda_runtime.h>
#include <math.h>

#define NN 50000
#define EE 800000
#define ET 850000          // EE + NN self loops
#define FH 128             // H * C
#define CC 64
#define NEG 0.2f
#define EPSN 1e-5f

// ---------------- scratch (static device, no allocation) ----------------
__device__ __align__(16) float g_xl[NN * FH];
__device__ __align__(16) float g_xr[NN * FH];
__device__ __align__(16) float g_xpre[NN * CC];
__device__ __align__(16) float g_xcur[NN * CC];
__device__ float g_cs[CC];
__device__ float g_css[CC];
__device__ int   g_deg[NN];
__device__ int   g_rowptr[NN + 1];
__device__ int   g_cursor[NN];
__device__ int   g_csrc[ET];

__device__ __forceinline__ float lrelu(float v) {
    return fmaxf(v, 0.f) + NEG * fminf(v, 0.f);
}

// packed f32x2 helpers (Blackwell FFMA2 path, PTX-only)
typedef unsigned long long u64t;
__device__ __forceinline__ u64t pk2(float lo, float hi) {
    u64t r; asm("mov.b64 %0, {%1,%2};" : "=l"(r) : "f"(lo), "f"(hi)); return r;
}
__device__ __forceinline__ void fma2(u64t& d, u64t a, u64t b) {
    asm("fma.rn.f32x2 %0, %1, %2, %3;" : "=l"(d) : "l"(a), "l"(b), "l"(d));
}

// ================= CSR build (once per launch, reused by all layers) ======
__global__ void k_zdeg() {
    int i = blockIdx.x * blockDim.x + threadIdx.x;
    if (i < NN) g_deg[i] = 0;
}

__global__ void k_histo(const int* __restrict__ ei) {
    int e = blockIdx.x * blockDim.x + threadIdx.x;
    if (e >= ET) return;
    int d = (e < EE) ? __ldg(ei + EE + e) : (e - EE);
    atomicAdd(&g_deg[d], 1);
}

// single-block exclusive scan over g_deg -> g_rowptr / g_cursor
__global__ void k_scan() {
    __shared__ int sh[1024];
    __shared__ int carry;
    int tid = threadIdx.x;
    if (tid == 0) carry = 0;
    __syncthreads();
    for (int base = 0; base < NN; base += 1024) {
        int i = base + tid;
        int v = (i < NN) ? g_deg[i] : 0;
        sh[tid] = v;
        __syncthreads();
        for (int off = 1; off < 1024; off <<= 1) {
            int t = (tid >= off) ? sh[tid - off] : 0;
            __syncthreads();
            sh[tid] += t;
            __syncthreads();
        }
        if (i < NN) {
            int excl = carry + sh[tid] - v;
            g_rowptr[i] = excl;
            g_cursor[i] = excl;
        }
        __syncthreads();
        if (tid == 0) carry += sh[1023];
        __syncthreads();
    }
    if (tid == 0) g_rowptr[NN] = carry;
}

__global__ void k_scatter(const int* __restrict__ ei) {
    int e = blockIdx.x * blockDim.x + threadIdx.x;
    if (e >= ET) return;
    int s, d;
    if (e < EE) { s = __ldg(ei + e); d = __ldg(ei + EE + e); }
    else        { s = e - EE; d = s; }
    int pos = atomicAdd(&g_cursor[d], 1);
    g_csrc[pos] = s;
}

// ================= per-layer kernels =====================================

// xl = x@Wl, xr = x@Wr with packed f32x2 FMA.
// block (32,8): lane -> 4 cols (2 f32x2 pairs), 4 nodes per thread, 32 nodes/block.
// Block 0 also zeroes the column-stat accumulators for this layer.
__global__ void k_gemm(const float* __restrict__ xin,
                       const float* __restrict__ Wl,
                       const float* __restrict__ Wr, int din) {
    if (blockIdx.x == 0 && threadIdx.y == 0 && threadIdx.x < 32) {
        g_cs[threadIdx.x] = 0.f;       g_css[threadIdx.x] = 0.f;
        g_cs[threadIdx.x + 32] = 0.f;  g_css[threadIdx.x + 32] = 0.f;
    }
    const float* xp = xin ? xin : g_xcur;
    int lane  = threadIdx.x;                       // 0..31
    int node0 = blockIdx.x * 32 + threadIdx.y * 4;
    if (node0 >= NN) return;

    u64t al[4][2], ar[4][2];
#pragma unroll
    for (int nn = 0; nn < 4; nn++) {
        al[nn][0] = al[nn][1] = 0ull;
        ar[nn][0] = ar[nn][1] = 0ull;
    }
    const float* x0 = xp + (size_t)node0 * din;
    for (int k = 0; k < din; k++) {
        ulonglong2 wl = *(const ulonglong2*)(Wl + k * FH + lane * 4);
        ulonglong2 wr = *(const ulonglong2*)(Wr + k * FH + lane * 4);
#pragma unroll
        for (int nn = 0; nn < 4; nn++) {
            float xv = __ldg(x0 + nn * din + k);
            u64t xx = pk2(xv, xv);
            fma2(al[nn][0], xx, wl.x);
            fma2(al[nn][1], xx, wl.y);
            fma2(ar[nn][0], xx, wr.x);
            fma2(ar[nn][1], xx, wr.y);
        }
    }
#pragma unroll
    for (int nn = 0; nn < 4; nn++) {
        ulonglong2 vl; vl.x = al[nn][0]; vl.y = al[nn][1];
        ulonglong2 vr; vr.x = ar[nn][0]; vr.y = ar[nn][1];
        *(ulonglong2*)(g_xl + (size_t)(node0 + nn) * FH + lane * 4) = vl;
        *(ulonglong2*)(g_xr + (size_t)(node0 + nn) * FH + lane * 4) = vr;
    }
}

// Fused attention: warp per node, BOTH heads per warp (lanes 0-15 head0,
// 16-31 head1, float4 per lane). Online softmax, prefetched gathers,
// fused head-mean + bias + column stats. Block 256 = 8 nodes.
__global__ void k_attn(const float* __restrict__ att,
                       const float* __restrict__ b) {
    __shared__ float sh[8][FH];
    __shared__ float ss[CC], sq[CC];
    int tid  = threadIdx.x;
    int warp = tid >> 5, lane = tid & 31;
    int node = blockIdx.x * 8 + warp;              // NN % 8 == 0

    if (tid < CC) { ss[tid] = 0.f; sq[tid] = 0.f; }

    float4 xr4 = *(const float4*)(g_xr + (size_t)node * FH + lane * 4);
    float4 w4  = *(const float4*)(att + lane * 4);

    float m = -INFINITY, z = 0.f;
    float4 acc = make_float4(0.f, 0.f, 0.f, 0.f);

    int i  = g_rowptr[node];
    int i1 = g_rowptr[node + 1];
    int   sN  = __ldg(g_csrc + i);                 // deg >= 1 (self loop)
    float4 xlN = *(const float4*)(g_xl + (size_t)sN * FH + lane * 4);

    while (i < i1) {
        float4 xl4 = xlN;
        i++;
        if (i < i1) {                              // prefetch next edge
            sN  = __ldg(g_csrc + i);
            xlN = *(const float4*)(g_xl + (size_t)sN * FH + lane * 4);
        }
        float p;
        p  = lrelu(xl4.x + xr4.x) * w4.x;
        p += lrelu(xl4.y + xr4.y) * w4.y;
        p += lrelu(xl4.z + xr4.z) * w4.z;
        p += lrelu(xl4.w + xr4.w) * w4.w;
        // reduce within each 16-lane half (head-separate)
        p += __shfl_xor_sync(0xffffffffu, p, 8);
        p += __shfl_xor_sync(0xffffffffu, p, 4);
        p += __shfl_xor_sync(0xffffffffu, p, 2);
        p += __shfl_xor_sync(0xffffffffu, p, 1);

        float mn = fmaxf(m, p);
        float c  = __expf(m - mn);
        float e  = __expf(p - mn);
        z = z * c + e;
        acc.x = acc.x * c + e * xl4.x;
        acc.y = acc.y * c + e * xl4.y;
        acc.z = acc.z * c + e * xl4.z;
        acc.w = acc.w * c + e * xl4.w;
        m = mn;
    }
    float iz = 1.f / z;
    sh[warp][lane * 4 + 0] = acc.x * iz;
    sh[warp][lane * 4 + 1] = acc.y * iz;
    sh[warp][lane * 4 + 2] = acc.z * iz;
    sh[warp][lane * 4 + 3] = acc.w * iz;
    __syncthreads();

    // 8 nodes x 64 cols = 512 outputs, 256 threads -> 2 each
#pragma unroll
    for (int rep = 0; rep < 2; rep++) {
        int idx = rep * 256 + tid;
        int nl = idx >> 6, c = idx & 63;
        float v = 0.5f * (sh[nl][c] + sh[nl][CC + c]) + __ldg(b + c);
        g_xpre[(size_t)(blockIdx.x * 8 + nl) * CC + c] = v;
        atomicAdd(&ss[c], v);
        atomicAdd(&sq[c], v * v);
    }
    __syncthreads();
    if (tid < CC) {
        atomicAdd(&g_cs[tid],  ss[tid]);
        atomicAdd(&g_css[tid], sq[tid]);
    }
}

// graph norm + relu
__global__ void k_norm(const float* __restrict__ gw,
                       const float* __restrict__ gb,
                       const float* __restrict__ gm,
                       float* __restrict__ out_ext) {
    float* out = out_ext ? out_ext : g_xcur;
    int idx = blockIdx.x * blockDim.x + threadIdx.x;
    int c = idx & 63;
    float inv = 1.f / (float)NN;
    float mu  = g_cs[c]  * inv;
    float msq = g_css[c] * inv;
    float ms  = __ldg(gm + c);
    float var = msq - 2.f * ms * mu * mu + ms * ms * mu * mu;
    float o = g_xpre[idx] - ms * mu;
    float y = __ldg(gw + c) * o * rsqrtf(var + EPSN) + __ldg(gb + c);
    out[idx] = fmaxf(y, 0.f);
}

// ---------------- launch ----------------
extern "C" void kernel_launch(void* const* d_in, const int* in_sizes, int n_in,
                              void* d_out, int out_size) {
    const float* x  = (const float*)d_in[0];
    const int*   ei = (const int*)d_in[1];
    float* out = (float*)d_out;

    const int edgeBlocks = (ET + 255) / 256;       // 3321
    const int gemmBlocks = (NN + 31) / 32;         // 1563
    const int attnBlocks = NN / 8;                 // 6250
    const int normBlocks = (NN * CC) / 256;        // 12500

    // CSR by dst, built once, reused by all 3 layers
    k_zdeg<<<(NN + 255) / 256, 256>>>();
    k_histo<<<edgeBlocks, 256>>>(ei);
    k_scan<<<1, 1024>>>();
    k_scatter<<<edgeBlocks, 256>>>(ei);

    const float* xin = x;
    int din = 3;
    for (int l = 0; l < 3; l++) {
        int base = 2 + 7 * l;
        const float* Wl  = (const float*)d_in[base + 0];
        const float* Wr  = (const float*)d_in[base + 1];
        const float* att = (const float*)d_in[base + 2];
        const float* b   = (const float*)d_in[base + 3];
        const float* gw  = (const float*)d_in[base + 4];
        const float* gb  = (const float*)d_in[base + 5];
        const float* gm  = (const float*)d_in[base + 6];

        k_gemm<<<gemmBlocks, dim3(32, 8)>>>(xin, Wl, Wr, din);
        k_attn<<<attnBlocks, 256>>>(att, b);
        k_norm<<<normBlocks, 256>>>(gw, gb, gm, (l == 2) ? out : nullptr);

        xin = nullptr;    // subsequent layers read g_xcur
        din = CC;
    }
}

// round 5
// speedup vs baseline: 3.8141x; 1.1169x over previous
#include <cuda_runtime.h>
#include <math.h>

#define NN 50000
#define EE 800000
#define ET 850000          // EE + NN self loops
#define FH 128             // H * C
#define CC 64
#define NEG 0.2f
#define EPSN 1e-5f

// ---------------- scratch (static device, no allocation) ----------------
__device__ __align__(16) float g_xl[NN * FH];
__device__ __align__(16) float g_xr[NN * FH];
__device__ __align__(16) float g_xpre[NN * CC];
__device__ float g_cs[3 * CC];
__device__ float g_css[3 * CC];
__device__ int   g_deg[NN];
__device__ int   g_rowptr[NN + 1];
__device__ int   g_cursor[NN];
__device__ int   g_csrc[ET];

__device__ __forceinline__ float lrelu(float v) {
    return fmaxf(v, 0.f) + NEG * fminf(v, 0.f);
}

// packed f32x2 helpers (Blackwell FFMA2 path, PTX-only)
typedef unsigned long long u64t;
__device__ __forceinline__ void fma2(u64t& d, u64t a, u64t b) {
    asm("fma.rn.f32x2 %0, %1, %2, %3;" : "=l"(d) : "l"(a), "l"(b), "l"(d));
}

// ================= CSR build (once per launch) ===========================
__global__ void k_zdeg() {
    int i = blockIdx.x * blockDim.x + threadIdx.x;
    if (i < NN) g_deg[i] = 0;
    if (i < 3 * CC) { g_cs[i] = 0.f; g_css[i] = 0.f; }
}

__global__ void k_histo(const int* __restrict__ ei) {
    int e = blockIdx.x * blockDim.x + threadIdx.x;
    if (e >= ET) return;
    int d = (e < EE) ? __ldg(ei + EE + e) : (e - EE);
    atomicAdd(&g_deg[d], 1);
}

// single-block exclusive scan via warp shuffles
__global__ void k_scan() {
    __shared__ int wsum[32];
    __shared__ int carry;
    int tid = threadIdx.x, lane = tid & 31, wid = tid >> 5;
    if (tid == 0) carry = 0;
    __syncthreads();
    for (int base = 0; base < NN; base += 1024) {
        int i = base + tid;
        int v = (i < NN) ? g_deg[i] : 0;
        int s = v;
#pragma unroll
        for (int off = 1; off < 32; off <<= 1) {
            int t = __shfl_up_sync(0xffffffffu, s, off);
            if (lane >= off) s += t;
        }
        if (lane == 31) wsum[wid] = s;
        __syncthreads();
        if (wid == 0) {
            int w = wsum[lane];
#pragma unroll
            for (int off = 1; off < 32; off <<= 1) {
                int t = __shfl_up_sync(0xffffffffu, w, off);
                if (lane >= off) w += t;
            }
            wsum[lane] = w;
        }
        __syncthreads();
        int boff = carry + (wid ? wsum[wid - 1] : 0);
        if (i < NN) {
            int ex = boff + s - v;
            g_rowptr[i] = ex;
            g_cursor[i] = ex;
        }
        __syncthreads();
        if (tid == 0) carry += wsum[31];
        __syncthreads();
    }
    if (tid == 0) g_rowptr[NN] = carry;
}

__global__ void k_scatter(const int* __restrict__ ei) {
    int e = blockIdx.x * blockDim.x + threadIdx.x;
    if (e >= ET) return;
    int s, d;
    if (e < EE) { s = __ldg(ei + e); d = __ldg(ei + EE + e); }
    else        { s = e - EE; d = s; }
    int pos = atomicAdd(&g_cursor[d], 1);
    g_csrc[pos] = s;
}

// ================= per-layer kernels =====================================

// xl = x@Wl, xr = x@Wr (f32x2 FMA). Block (32,4)=128 threads, 32 nodes/block,
// 8 nodes per thread-row. x tile staged in shared DUPLICATED (float2{v,v}),
// with previous layer's graph-norm + relu folded into the staging load
// (gw==null -> raw external input, layer 1).
__global__ void k_gemm(const float* __restrict__ xin,
                       const float* __restrict__ Wl,
                       const float* __restrict__ Wr, int din,
                       const float* __restrict__ gw,
                       const float* __restrict__ gb,
                       const float* __restrict__ gm,
                       const float* __restrict__ cs,
                       const float* __restrict__ css) {
    __shared__ float2 sx[32][CC];
    int lane = threadIdx.x;
    int tid  = threadIdx.y * 32 + lane;
    int nodeBase = blockIdx.x * 32;

    if (xin) {                         // layer 1, raw input, din small
        for (int idx = tid; idx < 32 * din; idx += 128) {
            int n = idx / din, k = idx % din;
            float v = (nodeBase + n < NN)
                    ? __ldg(xin + (size_t)(nodeBase + n) * din + k) : 0.f;
            sx[n][k] = make_float2(v, v);
        }
    } else {                           // din == 64: norm+relu fold
        const float invN = 1.f / (float)NN;
        for (int idx = tid; idx < 32 * CC; idx += 128) {
            int n = idx >> 6, c = idx & 63;
            float v = 0.f;
            if (nodeBase + n < NN) {
                float raw = g_xpre[(size_t)(nodeBase + n) * CC + c];
                float mu  = __ldg(cs + c)  * invN;
                float msq = __ldg(css + c) * invN;
                float ms  = __ldg(gm + c);
                float var = msq - 2.f * ms * mu * mu + ms * ms * mu * mu;
                float o = raw - ms * mu;
                v = fmaxf(__ldg(gw + c) * o * rsqrtf(var + EPSN) + __ldg(gb + c), 0.f);
            }
            sx[n][c] = make_float2(v, v);
        }
    }
    __syncthreads();

    int nrow = threadIdx.y * 8;        // first of this thread's 8 nodes
    u64t al[8][2], ar[8][2];
#pragma unroll
    for (int nn = 0; nn < 8; nn++) {
        al[nn][0] = al[nn][1] = 0ull;
        ar[nn][0] = ar[nn][1] = 0ull;
    }
    for (int k = 0; k < din; k++) {
        ulonglong2 wl = *(const ulonglong2*)(Wl + k * FH + lane * 4);
        ulonglong2 wr = *(const ulonglong2*)(Wr + k * FH + lane * 4);
#pragma unroll
        for (int nn = 0; nn < 8; nn++) {
            u64t xx = *(const u64t*)&sx[nrow + nn][k];   // broadcast LDS.64
            fma2(al[nn][0], xx, wl.x);
            fma2(al[nn][1], xx, wl.y);
            fma2(ar[nn][0], xx, wr.x);
            fma2(ar[nn][1], xx, wr.y);
        }
    }
#pragma unroll
    for (int nn = 0; nn < 8; nn++) {
        int node = nodeBase + nrow + nn;
        if (node < NN) {
            ulonglong2 vl; vl.x = al[nn][0]; vl.y = al[nn][1];
            ulonglong2 vr; vr.x = ar[nn][0]; vr.y = ar[nn][1];
            *(ulonglong2*)(g_xl + (size_t)node * FH + lane * 4) = vl;
            *(ulonglong2*)(g_xr + (size_t)node * FH + lane * 4) = vr;
        }
    }
}

// Fused attention: warp per node, both heads per warp (lanes 0-15 head0,
// 16-31 head1, float4/lane). Pairwise online softmax with pair-ahead
// prefetch (MLP=2). Fuses head-mean + bias + per-layer column stats.
__global__ void k_attn(const float* __restrict__ att,
                       const float* __restrict__ b,
                       float* __restrict__ cs,
                       float* __restrict__ css) {
    __shared__ float sh[8][FH];
    __shared__ float ss[CC], sq[CC];
    int tid  = threadIdx.x;
    int warp = tid >> 5, lane = tid & 31;
    int node = blockIdx.x * 8 + warp;              // NN % 8 == 0

    if (tid < CC) { ss[tid] = 0.f; sq[tid] = 0.f; }

    float4 xr4 = *(const float4*)(g_xr + (size_t)node * FH + lane * 4);
    float4 w4  = *(const float4*)(att + lane * 4);

    float m = -INFINITY, z = 0.f;
    float4 acc = make_float4(0.f, 0.f, 0.f, 0.f);

    int i  = g_rowptr[node];
    int i1 = g_rowptr[node + 1];
    // prologue: prefetch first pair (deg >= 1 from self loop)
    int sA = __ldg(g_csrc + i);
    int sB = (i + 1 < i1) ? __ldg(g_csrc + i + 1) : sA;
    float4 xA = *(const float4*)(g_xl + (size_t)sA * FH + lane * 4);
    float4 xB = *(const float4*)(g_xl + (size_t)sB * FH + lane * 4);

    while (i < i1) {
        bool has2 = (i + 1 < i1);
        float4 x0 = xA, x1 = xB;
        int inext = i + 2;
        if (inext < i1) {                          // prefetch next pair
            sA = __ldg(g_csrc + inext);
            sB = (inext + 1 < i1) ? __ldg(g_csrc + inext + 1) : sA;
            xA = *(const float4*)(g_xl + (size_t)sA * FH + lane * 4);
            xB = *(const float4*)(g_xl + (size_t)sB * FH + lane * 4);
        }
        float p0, p1;
        p0  = lrelu(x0.x + xr4.x) * w4.x;
        p0 += lrelu(x0.y + xr4.y) * w4.y;
        p0 += lrelu(x0.z + xr4.z) * w4.z;
        p0 += lrelu(x0.w + xr4.w) * w4.w;
        p1  = lrelu(x1.x + xr4.x) * w4.x;
        p1 += lrelu(x1.y + xr4.y) * w4.y;
        p1 += lrelu(x1.z + xr4.z) * w4.z;
        p1 += lrelu(x1.w + xr4.w) * w4.w;
#pragma unroll
        for (int off = 8; off >= 1; off >>= 1) {   // per-head 16-lane sums
            p0 += __shfl_xor_sync(0xffffffffu, p0, off);
            p1 += __shfl_xor_sync(0xffffffffu, p1, off);
        }
        if (has2) {
            float mn = fmaxf(m, fmaxf(p0, p1));
            float c  = __expf(m - mn);
            float e0 = __expf(p0 - mn);
            float e1 = __expf(p1 - mn);
            z = z * c + e0 + e1;
            acc.x = acc.x * c + e0 * x0.x + e1 * x1.x;
            acc.y = acc.y * c + e0 * x0.y + e1 * x1.y;
            acc.z = acc.z * c + e0 * x0.z + e1 * x1.z;
            acc.w = acc.w * c + e0 * x0.w + e1 * x1.w;
            m = mn;
        } else {
            float mn = fmaxf(m, p0);
            float c  = __expf(m - mn);
            float e0 = __expf(p0 - mn);
            z = z * c + e0;
            acc.x = acc.x * c + e0 * x0.x;
            acc.y = acc.y * c + e0 * x0.y;
            acc.z = acc.z * c + e0 * x0.z;
            acc.w = acc.w * c + e0 * x0.w;
            m = mn;
        }
        i = inext;
    }
    float iz = 1.f / z;
    sh[warp][lane * 4 + 0] = acc.x * iz;
    sh[warp][lane * 4 + 1] = acc.y * iz;
    sh[warp][lane * 4 + 2] = acc.z * iz;
    sh[warp][lane * 4 + 3] = acc.w * iz;
    __syncthreads();

#pragma unroll
    for (int rep = 0; rep < 2; rep++) {
        int idx = rep * 256 + tid;
        int nl = idx >> 6, c = idx & 63;
        float v = 0.5f * (sh[nl][c] + sh[nl][CC + c]) + __ldg(b + c);
        g_xpre[(size_t)(blockIdx.x * 8 + nl) * CC + c] = v;
        atomicAdd(&ss[c], v);
        atomicAdd(&sq[c], v * v);
    }
    __syncthreads();
    if (tid < CC) {
        atomicAdd(&cs[tid],  ss[tid]);
        atomicAdd(&css[tid], sq[tid]);
    }
}

// final graph norm + relu (layer 3 only; layers 1-2 folded into k_gemm)
__global__ void k_norm(const float* __restrict__ gw,
                       const float* __restrict__ gb,
                       const float* __restrict__ gm,
                       const float* __restrict__ cs,
                       const float* __restrict__ css,
                       float* __restrict__ out) {
    int idx = blockIdx.x * blockDim.x + threadIdx.x;
    int c = idx & 63;
    float inv = 1.f / (float)NN;
    float mu  = __ldg(cs + c)  * inv;
    float msq = __ldg(css + c) * inv;
    float ms  = __ldg(gm + c);
    float var = msq - 2.f * ms * mu * mu + ms * ms * mu * mu;
    float o = g_xpre[idx] - ms * mu;
    float y = __ldg(gw + c) * o * rsqrtf(var + EPSN) + __ldg(gb + c);
    out[idx] = fmaxf(y, 0.f);
}

// ---------------- launch ----------------
extern "C" void kernel_launch(void* const* d_in, const int* in_sizes, int n_in,
                              void* d_out, int out_size) {
    const float* x  = (const float*)d_in[0];
    const int*   ei = (const int*)d_in[1];
    float* out = (float*)d_out;

    float* cs0;  float* css0;
    cudaGetSymbolAddress((void**)&cs0,  g_cs);
    cudaGetSymbolAddress((void**)&css0, g_css);

    const int edgeBlocks = (ET + 255) / 256;       // 3321
    const int gemmBlocks = (NN + 31) / 32;         // 1563
    const int attnBlocks = NN / 8;                 // 6250
    const int normBlocks = (NN * CC) / 256;        // 12500

    // CSR by dst + zero stats, built once, reused by all 3 layers
    k_zdeg<<<(NN + 255) / 256, 256>>>();
    k_histo<<<edgeBlocks, 256>>>(ei);
    k_scan<<<1, 1024>>>();
    k_scatter<<<edgeBlocks, 256>>>(ei);

    const float* xin = x;
    int din = 3;
    const float *pgw = nullptr, *pgb = nullptr, *pgm = nullptr;
    for (int l = 0; l < 3; l++) {
        int base = 2 + 7 * l;
        const float* Wl  = (const float*)d_in[base + 0];
        const float* Wr  = (const float*)d_in[base + 1];
        const float* att = (const float*)d_in[base + 2];
        const float* b   = (const float*)d_in[base + 3];

        float* csP  = cs0  + (l > 0 ? (l - 1) * CC : 0);
        float* cssP = css0 + (l > 0 ? (l - 1) * CC : 0);
        k_gemm<<<gemmBlocks, dim3(32, 4)>>>(xin, Wl, Wr, din,
                                            pgw, pgb, pgm, csP, cssP);
        k_attn<<<attnBlocks, 256>>>(att, b, cs0 + l * CC, css0 + l * CC);

        pgw = (const float*)d_in[base + 4];
        pgb = (const float*)d_in[base + 5];
        pgm = (const float*)d_in[base + 6];
        xin = nullptr;
        din = CC;
    }
    k_norm<<<normBlocks, 256>>>(pgw, pgb, pgm,
                                cs0 + 2 * CC, css0 + 2 * CC, out);
}

// round 6
// speedup vs baseline: 4.1123x; 1.0782x over previous
#include <cuda_runtime.h>
#include <math.h>

#define NN 50000
#define EE 800000
#define ET 850000          // EE + NN self loops
#define FH 128             // H * C
#define CC 64
#define NEG 0.2f
#define EPSN 1e-5f

// ---------------- scratch (static device, no allocation) ----------------
__device__ __align__(16) float g_xl[NN * FH];
__device__ __align__(16) float g_xr[NN * FH];
__device__ __align__(16) float g_xpre[NN * CC];
__device__ float g_cs[3 * CC];
__device__ float g_css[3 * CC];
__device__ int   g_deg[NN];
__device__ int   g_rowptr[NN + 1];
__device__ int   g_cursor[NN];
__device__ int   g_csrc[ET];

__device__ __forceinline__ float lrelu(float v) {
    return fmaxf(v, 0.f) + NEG * fminf(v, 0.f);
}

// packed f32x2 helpers (Blackwell FFMA2 path, PTX-only)
typedef unsigned long long u64t;
__device__ __forceinline__ void fma2(u64t& d, u64t a, u64t b) {
    asm("fma.rn.f32x2 %0, %1, %2, %3;" : "=l"(d) : "l"(a), "l"(b), "l"(d));
}

// ================= CSR build =============================================
__global__ void k_histo(const int* __restrict__ ei) {
    int e = blockIdx.x * blockDim.x + threadIdx.x;
    if (e >= ET) return;
    int d = (e < EE) ? __ldg(ei + EE + e) : (e - EE);
    atomicAdd(&g_deg[d], 1);
}

// single-block exclusive scan via warp shuffles
__global__ void k_scan() {
    __shared__ int wsum[32];
    __shared__ int carry;
    int tid = threadIdx.x, lane = tid & 31, wid = tid >> 5;
    if (tid == 0) carry = 0;
    __syncthreads();
    for (int base = 0; base < NN; base += 1024) {
        int i = base + tid;
        int v = (i < NN) ? g_deg[i] : 0;
        int s = v;
#pragma unroll
        for (int off = 1; off < 32; off <<= 1) {
            int t = __shfl_up_sync(0xffffffffu, s, off);
            if (lane >= off) s += t;
        }
        if (lane == 31) wsum[wid] = s;
        __syncthreads();
        if (wid == 0) {
            int w = wsum[lane];
#pragma unroll
            for (int off = 1; off < 32; off <<= 1) {
                int t = __shfl_up_sync(0xffffffffu, w, off);
                if (lane >= off) w += t;
            }
            wsum[lane] = w;
        }
        __syncthreads();
        int boff = carry + (wid ? wsum[wid - 1] : 0);
        if (i < NN) {
            int ex = boff + s - v;
            g_rowptr[i] = ex;
            g_cursor[i] = ex;
        }
        __syncthreads();
        if (tid == 0) carry += wsum[31];
        __syncthreads();
    }
    if (tid == 0) g_rowptr[NN] = carry;
}

__global__ void k_scatter(const int* __restrict__ ei) {
    int e = blockIdx.x * blockDim.x + threadIdx.x;
    if (e >= ET) return;
    int s, d;
    if (e < EE) { s = __ldg(ei + e); d = __ldg(ei + EE + e); }
    else        { s = e - EE; d = s; }
    int pos = atomicAdd(&g_cursor[d], 1);
    g_csrc[pos] = s;
}

// ================= per-layer kernels =====================================

// xl = x@Wl, xr = x@Wr (f32x2 FMA). Block (32,4)=128 threads, 32 nodes/block,
// 8 nodes/thread-row. x tile staged in shared duplicated (float2{v,v}), with
// previous layer's graph-norm + relu folded into the staging load.
__global__ void k_gemm(const float* __restrict__ xin,
                       const float* __restrict__ Wl,
                       const float* __restrict__ Wr, int din,
                       const float* __restrict__ gw,
                       const float* __restrict__ gb,
                       const float* __restrict__ gm,
                       const float* __restrict__ cs,
                       const float* __restrict__ css) {
    __shared__ float2 sx[32][CC];
    int lane = threadIdx.x;
    int tid  = threadIdx.y * 32 + lane;
    int nodeBase = blockIdx.x * 32;

    if (xin) {                         // layer 1: raw external input
        for (int idx = tid; idx < 32 * din; idx += 128) {
            int n = idx / din, k = idx % din;
            float v = (nodeBase + n < NN)
                    ? __ldg(xin + (size_t)(nodeBase + n) * din + k) : 0.f;
            sx[n][k] = make_float2(v, v);
        }
    } else {                           // din == 64: norm+relu fold
        const float invN = 1.f / (float)NN;
        for (int idx = tid; idx < 32 * CC; idx += 128) {
            int n = idx >> 6, c = idx & 63;
            float v = 0.f;
            if (nodeBase + n < NN) {
                float raw = g_xpre[(size_t)(nodeBase + n) * CC + c];
                float mu  = __ldg(cs + c)  * invN;
                float msq = __ldg(css + c) * invN;
                float ms  = __ldg(gm + c);
                float var = msq - 2.f * ms * mu * mu + ms * ms * mu * mu;
                float o = raw - ms * mu;
                v = fmaxf(__ldg(gw + c) * o * rsqrtf(var + EPSN) + __ldg(gb + c), 0.f);
            }
            sx[n][c] = make_float2(v, v);
        }
    }
    __syncthreads();

    int nrow = threadIdx.y * 8;
    u64t al[8][2], ar[8][2];
#pragma unroll
    for (int nn = 0; nn < 8; nn++) {
        al[nn][0] = al[nn][1] = 0ull;
        ar[nn][0] = ar[nn][1] = 0ull;
    }
    for (int k = 0; k < din; k++) {
        ulonglong2 wl = *(const ulonglong2*)(Wl + k * FH + lane * 4);
        ulonglong2 wr = *(const ulonglong2*)(Wr + k * FH + lane * 4);
#pragma unroll
        for (int nn = 0; nn < 8; nn++) {
            u64t xx = *(const u64t*)&sx[nrow + nn][k];   // broadcast LDS.64
            fma2(al[nn][0], xx, wl.x);
            fma2(al[nn][1], xx, wl.y);
            fma2(ar[nn][0], xx, wr.x);
            fma2(ar[nn][1], xx, wr.y);
        }
    }
#pragma unroll
    for (int nn = 0; nn < 8; nn++) {
        int node = nodeBase + nrow + nn;
        if (node < NN) {
            ulonglong2 vl; vl.x = al[nn][0]; vl.y = al[nn][1];
            ulonglong2 vr; vr.x = ar[nn][0]; vr.y = ar[nn][1];
            *(ulonglong2*)(g_xl + (size_t)node * FH + lane * 4) = vl;
            *(ulonglong2*)(g_xr + (size_t)node * FH + lane * 4) = vr;
        }
    }
}

// Fused attention v3: warp per node, TWO parallel edge-streams per warp
// (lanes 0-15 even CSR slots, 16-31 odd slots). Within a 16-lane half:
// 8 lanes/head, 8 floats/lane. Independent online softmax per half,
// associative merge at the end (shfl_xor 16). Halves the loop-carried
// rescale chain per warp. Fuses head-mean + bias + column stats.
__global__ void k_attn(const float* __restrict__ att,
                       const float* __restrict__ b,
                       float* __restrict__ cs,
                       float* __restrict__ css) {
    __shared__ float sh[8][FH];
    __shared__ float ss[CC], sq[CC];
    const unsigned F = 0xffffffffu;
    int tid  = threadIdx.x;
    int warp = tid >> 5, lane = tid & 31;
    int node = blockIdx.x * 8 + warp;              // NN % 8 == 0

    if (tid < CC) { ss[tid] = 0.f; sq[tid] = 0.f; }

    int h16 = lane >> 4;                 // edge-stream (parity)
    int sub = lane & 15;
    int cbase = (sub >> 3) * CC + (sub & 7) * 8;   // head*64 + q*8

    float4 xr_a = *(const float4*)(g_xr + (size_t)node * FH + cbase);
    float4 xr_b = *(const float4*)(g_xr + (size_t)node * FH + cbase + 4);
    float4 w_a  = *(const float4*)(att + cbase);
    float4 w_b  = *(const float4*)(att + cbase + 4);

    int i0 = g_rowptr[node], i1 = g_rowptr[node + 1];
    int nIter = (i1 - i0 + 1) >> 1;

    float m = -INFINITY, z = 0.f;
    float4 A = make_float4(0.f, 0.f, 0.f, 0.f);
    float4 B = make_float4(0.f, 0.f, 0.f, 0.f);

    int idx = i0 + h16;
    int sp = __ldg(g_csrc + min(idx, i1 - 1));
    float4 pa = *(const float4*)(g_xl + (size_t)sp * FH + cbase);
    float4 pb = *(const float4*)(g_xl + (size_t)sp * FH + cbase + 4);

    for (int it = 0; it < nIter; it++) {
        bool act = idx < i1;
        float4 x0 = pa, x1 = pb;
        idx += 2;
        int sn = __ldg(g_csrc + min(idx, i1 - 1));   // prefetch next
        pa = *(const float4*)(g_xl + (size_t)sn * FH + cbase);
        pb = *(const float4*)(g_xl + (size_t)sn * FH + cbase + 4);

        float p;
        p  = lrelu(x0.x + xr_a.x) * w_a.x;
        p += lrelu(x0.y + xr_a.y) * w_a.y;
        p += lrelu(x0.z + xr_a.z) * w_a.z;
        p += lrelu(x0.w + xr_a.w) * w_a.w;
        p += lrelu(x1.x + xr_b.x) * w_b.x;
        p += lrelu(x1.y + xr_b.y) * w_b.y;
        p += lrelu(x1.z + xr_b.z) * w_b.z;
        p += lrelu(x1.w + xr_b.w) * w_b.w;
        p += __shfl_xor_sync(F, p, 4);     // reduce within 8-lane head group
        p += __shfl_xor_sync(F, p, 2);
        p += __shfl_xor_sync(F, p, 1);

        if (act) {
            float mn = fmaxf(m, p);
            float c  = __expf(m - mn);
            float e  = __expf(p - mn);
            z = z * c + e;
            A.x = A.x * c + e * x0.x;  A.y = A.y * c + e * x0.y;
            A.z = A.z * c + e * x0.z;  A.w = A.w * c + e * x0.w;
            B.x = B.x * c + e * x1.x;  B.y = B.y * c + e * x1.y;
            B.z = B.z * c + e * x1.z;  B.w = B.w * c + e * x1.w;
            m = mn;
        }
    }

    // merge the two halves' softmax states (per head group)
    float mo = __shfl_xor_sync(F, m, 16);
    float zo = __shfl_xor_sync(F, z, 16);
    float4 Ao, Bo;
    Ao.x = __shfl_xor_sync(F, A.x, 16);  Ao.y = __shfl_xor_sync(F, A.y, 16);
    Ao.z = __shfl_xor_sync(F, A.z, 16);  Ao.w = __shfl_xor_sync(F, A.w, 16);
    Bo.x = __shfl_xor_sync(F, B.x, 16);  Bo.y = __shfl_xor_sync(F, B.y, 16);
    Bo.z = __shfl_xor_sync(F, B.z, 16);  Bo.w = __shfl_xor_sync(F, B.w, 16);

    float mn = fmaxf(m, mo);
    float c0 = __expf(m - mn);
    float c1 = __expf(mo - mn);
    float iz = 1.f / (z * c0 + zo * c1);

    if (h16 == 0) {
        sh[warp][cbase + 0] = (A.x * c0 + Ao.x * c1) * iz;
        sh[warp][cbase + 1] = (A.y * c0 + Ao.y * c1) * iz;
        sh[warp][cbase + 2] = (A.z * c0 + Ao.z * c1) * iz;
        sh[warp][cbase + 3] = (A.w * c0 + Ao.w * c1) * iz;
        sh[warp][cbase + 4] = (B.x * c0 + Bo.x * c1) * iz;
        sh[warp][cbase + 5] = (B.y * c0 + Bo.y * c1) * iz;
        sh[warp][cbase + 6] = (B.z * c0 + Bo.z * c1) * iz;
        sh[warp][cbase + 7] = (B.w * c0 + Bo.w * c1) * iz;
    }
    __syncthreads();

#pragma unroll
    for (int rep = 0; rep < 2; rep++) {
        int idx2 = rep * 256 + tid;
        int nl = idx2 >> 6, c = idx2 & 63;
        float v = 0.5f * (sh[nl][c] + sh[nl][CC + c]) + __ldg(b + c);
        g_xpre[(size_t)(blockIdx.x * 8 + nl) * CC + c] = v;
        atomicAdd(&ss[c], v);
        atomicAdd(&sq[c], v * v);
    }
    __syncthreads();
    if (tid < CC) {
        atomicAdd(&cs[tid],  ss[tid]);
        atomicAdd(&css[tid], sq[tid]);
    }
}

// final graph norm + relu (layer 3 only)
__global__ void k_norm(const float* __restrict__ gw,
                       const float* __restrict__ gb,
                       const float* __restrict__ gm,
                       const float* __restrict__ cs,
                       const float* __restrict__ css,
                       float* __restrict__ out) {
    int idx = blockIdx.x * blockDim.x + threadIdx.x;
    int c = idx & 63;
    float inv = 1.f / (float)NN;
    float mu  = __ldg(cs + c)  * inv;
    float msq = __ldg(css + c) * inv;
    float ms  = __ldg(gm + c);
    float var = msq - 2.f * ms * mu * mu + ms * ms * mu * mu;
    float o = g_xpre[idx] - ms * mu;
    float y = __ldg(gw + c) * o * rsqrtf(var + EPSN) + __ldg(gb + c);
    out[idx] = fmaxf(y, 0.f);
}

// ---------------- launch ----------------
extern "C" void kernel_launch(void* const* d_in, const int* in_sizes, int n_in,
                              void* d_out, int out_size) {
    const float* x  = (const float*)d_in[0];
    const int*   ei = (const int*)d_in[1];
    float* out = (float*)d_out;

    float *cs0, *css0; int* dDeg;
    cudaGetSymbolAddress((void**)&cs0,  g_cs);
    cudaGetSymbolAddress((void**)&css0, g_css);
    cudaGetSymbolAddress((void**)&dDeg, g_deg);

    // one-time infra (host objects only; no device memory)
    static cudaStream_t s2 = nullptr;
    static cudaEvent_t evA = nullptr, evB = nullptr;
    if (!s2) {
        cudaStreamCreateWithFlags(&s2, cudaStreamNonBlocking);
        cudaEventCreateWithFlags(&evA, cudaEventDisableTiming);
        cudaEventCreateWithFlags(&evB, cudaEventDisableTiming);
    }

    const int edgeBlocks = (ET + 255) / 256;       // 3321
    const int gemmBlocks = (NN + 31) / 32;         // 1563
    const int attnBlocks = NN / 8;                 // 6250
    const int normBlocks = (NN * CC) / 256;        // 12500

    // fork: CSR build on s2, overlapped with layer-1 GEMM on main stream
    cudaEventRecord(evA, 0);
    cudaStreamWaitEvent(s2, evA, 0);
    cudaMemsetAsync(dDeg, 0, NN * sizeof(int), s2);
    k_histo<<<edgeBlocks, 256, 0, s2>>>(ei);
    k_scan<<<1, 1024, 0, s2>>>();
    k_scatter<<<edgeBlocks, 256, 0, s2>>>(ei);
    cudaEventRecord(evB, s2);

    cudaMemsetAsync(cs0,  0, 3 * CC * sizeof(float), 0);
    cudaMemsetAsync(css0, 0, 3 * CC * sizeof(float), 0);

    const float* xin = x;
    int din = 3;
    const float *pgw = nullptr, *pgb = nullptr, *pgm = nullptr;
    for (int l = 0; l < 3; l++) {
        int base = 2 + 7 * l;
        const float* Wl  = (const float*)d_in[base + 0];
        const float* Wr  = (const float*)d_in[base + 1];
        const float* att = (const float*)d_in[base + 2];
        const float* b   = (const float*)d_in[base + 3];

        float* csP  = cs0  + (l > 0 ? (l - 1) * CC : 0);
        float* cssP = css0 + (l > 0 ? (l - 1) * CC : 0);
        k_gemm<<<gemmBlocks, dim3(32, 4)>>>(xin, Wl, Wr, din,
                                            pgw, pgb, pgm, csP, cssP);
        if (l == 0) cudaStreamWaitEvent(0, evB, 0);   // join CSR before attn1
        k_attn<<<attnBlocks, 256>>>(att, b, cs0 + l * CC, css0 + l * CC);

        pgw = (const float*)d_in[base + 4];
        pgb = (const float*)d_in[base + 5];
        pgm = (const float*)d_in[base + 6];
        xin = nullptr;
        din = CC;
    }
    k_norm<<<normBlocks, 256>>>(pgw, pgb, pgm,
                                cs0 + 2 * CC, css0 + 2 * CC, out);
}